// round 1
// baseline (speedup 1.0000x reference)
#include <cuda_runtime.h>
#include <cstdint>
#include <cstddef>

// Problem constants
#define BB    32
#define TT    2048
#define FIN   63
#define FDIM  64
#define LUDIM 640
#define NCH   16      // number of t-chunks for the parallel scan
#define TC    128     // timesteps per chunk  (NCH*TC == TT)
#define NCHAIN 2048   // B*U chains

// GEMM tiling
#define BT   128      // t rows per block
#define BLU  128      // lu cols per block
#define TPAD 132      // padded t stride for f-major X tile (multiple of 4, avoids worst bank conflicts)

// Scratch (static device globals; allocation-free per harness rules)
__device__ float g_P[(size_t)BB * TT * LUDIM];      // P[b][t][l*64+u], 167.8 MB
__device__ float g_W[(size_t)NCH * 17 * NCHAIN];    // per-chunk affine coefficients, 2.2 MB

// ---------------- f32x2 helpers (Blackwell packed fp32) ----------------
__device__ __forceinline__ unsigned long long splat2(float x) {
    unsigned long long r;
    asm("mov.b64 %0, {%1,%1};" : "=l"(r) : "f"(x));
    return r;
}
__device__ __forceinline__ void ffma2(unsigned long long &a, unsigned long long x, unsigned long long k) {
    asm("fma.rn.f32x2 %0, %1, %2, %0;" : "+l"(a) : "l"(x), "l"(k));
}
__device__ __forceinline__ float2 unpack2(unsigned long long v) {
    float2 r;
    asm("mov.b64 {%0,%1}, %2;" : "=f"(r.x), "=f"(r.y) : "l"(v));
    return r;
}

// ---------------- Kernel 1: P = X @ K  (X = [x | time]) ----------------
// Grid: (TT/BT, LUDIM/BLU, BB). Block: 256 threads (tx=tid&15 over lu, ty=tid>>4 over t).
// Thread tile: 8 t-rows x 8 lu-cols, accumulated as f32x2 pairs over lu.
extern "C" __global__ void __launch_bounds__(256, 2)
lrsig_gemm(const float* __restrict__ x, const float* __restrict__ kern)
{
    extern __shared__ float smem[];
    float* sX = smem;                 // [f][TPAD]  (f-major, padded)
    float* sK = smem + FDIM * TPAD;   // [f][BLU]

    const int tid = threadIdx.x;
    const int tx  = tid & 15;
    const int ty  = tid >> 4;
    const int t0  = blockIdx.x * BT;
    const int lu0 = blockIdx.y * BLU;
    const int b   = blockIdx.z;

    // Load X tile (coalesced over f), store f-major (transposed) into padded smem.
    // f == 63 is the synthetic time feature: t*(2/(T-1)) - 1.
    for (int e = tid; e < BT * FDIM; e += 256) {
        int f  = e & 63;
        int tl = e >> 6;
        int t  = t0 + tl;
        float v;
        if (f < FIN) v = x[((size_t)b * TT + t) * FIN + f];
        else         v = (float)t * (2.0f / 2047.0f) - 1.0f;
        sX[f * TPAD + tl] = v;
    }
    // Load K tile: kern[f][lu0 + j] (contiguous over lu) -> sK[f*BLU + j]
    for (int e = tid; e < FDIM * BLU; e += 256) {
        int f = e >> 7;
        int j = e & 127;
        sK[e] = kern[f * LUDIM + lu0 + j];
    }
    __syncthreads();

    unsigned long long acc[8][4];
#pragma unroll
    for (int r = 0; r < 8; r++)
#pragma unroll
        for (int p = 0; p < 4; p++) acc[r][p] = 0ULL;

    const float4*     X4 = reinterpret_cast<const float4*>(sX);
    const ulonglong2* K2 = reinterpret_cast<const ulonglong2*>(sK);

#pragma unroll 8
    for (int f = 0; f < FDIM; f++) {
        float4 xa = X4[f * (TPAD / 4) + ty * 2];       // t = ty*8 .. ty*8+3
        float4 xb = X4[f * (TPAD / 4) + ty * 2 + 1];   // t = ty*8+4 .. ty*8+7
        ulonglong2 k0 = K2[f * 32 + tx];               // lu = 4*tx   .. 4*tx+3
        ulonglong2 k1 = K2[f * 32 + 16 + tx];          // lu = 64+4*tx .. 64+4*tx+3
        unsigned long long x2[8];
        x2[0] = splat2(xa.x); x2[1] = splat2(xa.y);
        x2[2] = splat2(xa.z); x2[3] = splat2(xa.w);
        x2[4] = splat2(xb.x); x2[5] = splat2(xb.y);
        x2[6] = splat2(xb.z); x2[7] = splat2(xb.w);
#pragma unroll
        for (int r = 0; r < 8; r++) {
            ffma2(acc[r][0], x2[r], k0.x);
            ffma2(acc[r][1], x2[r], k0.y);
            ffma2(acc[r][2], x2[r], k1.x);
            ffma2(acc[r][3], x2[r], k1.y);
        }
    }

    // Write P[b][t][lu0 + ...]; float4 stores, coalesced across tx.
#pragma unroll
    for (int r = 0; r < 8; r++) {
        int t = t0 + ty * 8 + r;
        float* op = g_P + ((size_t)b * TT + t) * LUDIM + lu0;
#pragma unroll
        for (int c = 0; c < 2; c++) {
            float2 a  = unpack2(acc[r][2 * c]);
            float2 bv = unpack2(acc[r][2 * c + 1]);
            float4 o = make_float4(a.x, a.y, bv.x, bv.y);
            reinterpret_cast<float4*>(op + 64 * c + 4 * tx)[0] = o;
        }
    }
}

// ---------------- Kernel 2: per-chunk scan coefficients ----------------
// One thread per (chain, chunk). Computes the 17 affine coefficients of this
// chunk's action on the signature state (Chen identity / chunked scan).
// m_l[t] = P[t] - P[t-1], with m[0] = 0 (prev initialized to P[0] for chunk 0).
extern "C" __global__ void __launch_bounds__(256)
lrsig_scan(void)
{
    const int c     = blockIdx.x;
    const int chain = blockIdx.y * 256 + threadIdx.x;
    const int b = chain >> 6;
    const int u = chain & 63;

    const float* base = g_P + (size_t)b * TT * LUDIM + u;
    const int t0 = c * TC;
    const int tp = (c == 0) ? 0 : (t0 - 1);

    float prev[10];
#pragma unroll
    for (int l = 0; l < 10; l++) prev[l] = base[(size_t)tp * LUDIM + l * 64];

    float e1=0.f,e3=0.f,e4=0.f,e43=0.f,e6=0.f,e7=0.f,e76=0.f,e8=0.f,e87=0.f,e876=0.f;
    float S2=0.f,S5=0.f,S9=0.f,W21=0.f,W54=0.f,W543=0.f,W98=0.f,W987=0.f,W9876=0.f,y0=0.f;

    for (int i = 0; i < TC; i++) {
        const float* p = base + (size_t)(t0 + i) * LUDIM;
        float m[10];
#pragma unroll
        for (int l = 0; l < 10; l++) {
            float v = p[l * 64];
            m[l] = v - prev[l];
            prev[l] = v;
        }
        // All RHS below use pre-update (exclusive) values.
        y0   += m[0];
        W21   = fmaf(m[2], e1,   W21);   S2 += m[2];
        W54   = fmaf(m[5], e4,   W54);
        W543  = fmaf(m[5], e43,  W543);  S5 += m[5];
        W98   = fmaf(m[9], e8,   W98);
        W987  = fmaf(m[9], e87,  W987);
        W9876 = fmaf(m[9], e876, W9876); S9 += m[9];
        e43   = fmaf(m[4], e3,   e43);
        e876  = fmaf(m[8], e76,  e876);
        e87   = fmaf(m[8], e7,   e87);
        e76   = fmaf(m[7], e6,   e76);
        e1 += m[1]; e3 += m[3]; e4 += m[4];
        e6 += m[6]; e7 += m[7]; e8 += m[8];
    }

    float* w = g_W + (size_t)c * 17 * NCHAIN + chain;
    w[ 0 * NCHAIN] = y0 + W21 + W543 + W9876;  // state-independent Y contribution
    w[ 1 * NCHAIN] = S2;   w[ 2 * NCHAIN] = S5;   w[ 3 * NCHAIN] = S9;
    w[ 4 * NCHAIN] = W54;  w[ 5 * NCHAIN] = W98;  w[ 6 * NCHAIN] = W987;
    w[ 7 * NCHAIN] = e1;   w[ 8 * NCHAIN] = e3;   w[ 9 * NCHAIN] = e4;
    w[10 * NCHAIN] = e43;  w[11 * NCHAIN] = e6;   w[12 * NCHAIN] = e7;
    w[13 * NCHAIN] = e76;  w[14 * NCHAIN] = e8;   w[15 * NCHAIN] = e87;
    w[16 * NCHAIN] = e876;
}

// ---------------- Kernel 3: fold chunks per chain ----------------
extern "C" __global__ void __launch_bounds__(256)
lrsig_combine(float* __restrict__ out)
{
    const int chain = blockIdx.x * 256 + threadIdx.x;
    float y = 0.f, s1 = 0.f, s3 = 0.f, sa = 0.f, s6 = 0.f, sb = 0.f, sc = 0.f;

    for (int c = 0; c < NCH; c++) {
        const float* w = g_W + (size_t)c * 17 * NCHAIN + chain;
        float Y0   = w[ 0 * NCHAIN];
        float S2   = w[ 1 * NCHAIN], S5  = w[ 2 * NCHAIN], S9  = w[ 3 * NCHAIN];
        float W54  = w[ 4 * NCHAIN], W98 = w[ 5 * NCHAIN], W987= w[ 6 * NCHAIN];
        float E1   = w[ 7 * NCHAIN], E3  = w[ 8 * NCHAIN], E4  = w[ 9 * NCHAIN];
        float E43  = w[10 * NCHAIN], E6  = w[11 * NCHAIN], E7  = w[12 * NCHAIN];
        float E76  = w[13 * NCHAIN], E8  = w[14 * NCHAIN], E87 = w[15 * NCHAIN];
        float E876 = w[16 * NCHAIN];

        // Y contribution uses pre-chunk state
        y += Y0 + s1 * S2 + sa * S5 + s3 * W54 + sc * S9 + sb * W98 + s6 * W987;
        // State transition (note update order: sc before sb before s6, sa before s3)
        sc += sb * E8 + s6 * E87 + E876;
        sb += s6 * E7 + E76;
        sa += s3 * E4 + E43;
        s1 += E1; s3 += E3; s6 += E6;
    }
    out[chain] = y;   // out[b*64 + u] == Y[b][u]
}

// ---------------- Launch ----------------
extern "C" void kernel_launch(void* const* d_in, const int* in_sizes, int n_in,
                              void* d_out, int out_size)
{
    const float* x    = (const float*)d_in[0];  // (32, 2048, 63) f32
    const float* kern = (const float*)d_in[1];  // (64, 10, 64)  f32

    const size_t smem_bytes = (size_t)(FDIM * TPAD + FDIM * BLU) * sizeof(float); // 66,560 B
    cudaFuncSetAttribute(lrsig_gemm, cudaFuncAttributeMaxDynamicSharedMemorySize,
                         (int)smem_bytes);

    lrsig_gemm<<<dim3(TT / BT, LUDIM / BLU, BB), 256, smem_bytes>>>(x, kern);
    lrsig_scan<<<dim3(NCH, NCHAIN / 256), 256>>>();
    lrsig_combine<<<NCHAIN / 256, 256>>>((float*)d_out);
}